// round 16
// baseline (speedup 1.0000x reference)
#include <cuda_runtime.h>
#include <cuda_fp16.h>
#include <cstdint>

#define NN 20000
#define NE 300000
#define HD 256
#define MAXDEG 96

// ---------------- scratch (device globals; referenced ONLY in device code) --
__device__ int   g_cnt[NN];
__device__ __align__(16) float g_inv[NN];
__device__ __align__(16) float g_aggr[NN * HD];   // P2 (proj output)
__device__ __align__(16) float g_hA[NN * HD];     // layer1 h fp32 (for gather0)
__device__ __align__(16) float g_hB[NN * HD];     // layer2 h fp32 (for gather1); later P1
__device__ int g_row[NE];
__device__ int g_col[NE];
__device__ int g_elist[NN * MAXDEG];
// packed fp16 activations, K-pair-major: [node][k2]
__device__ __align__(16) uint32_t g_pAh[NN * 128], g_pAl[NN * 128]; // layer1 h, then layer3 h
__device__ __align__(16) uint32_t g_pBh[NN * 128], g_pBl[NN * 128]; // layer2 h
__device__ __align__(16) uint32_t g_pGh[NN * 128], g_pGl[NN * 128]; // gathered aggr
// packed fp16 weights (hi/lo), K-pair-major
// order: 0=Wl2 1=Wr2 2=Wl3 3=Wr3 4=W1a 5=W1b (each 128x256 uint32)
__device__ __align__(16) uint32_t g_wph[6 * 32768];
__device__ __align__(16) uint32_t g_wpl[6 * 32768];
__device__ __align__(16) uint32_t g_w2p[16384];   // W2 [128 k2][128 n]

__device__ __forceinline__ uint32_t pack2h(float e0, float e1) {
    __half h0 = __float2half_rn(e0), h1 = __float2half_rn(e1);
    return (uint32_t)__half_as_ushort(h0) | ((uint32_t)__half_as_ushort(h1) << 16);
}
__device__ __forceinline__ void packhl(float e0, float e1, uint32_t& hi, uint32_t& lo) {
    __half h0 = __float2half_rn(e0), h1 = __float2half_rn(e1);
    hi = (uint32_t)__half_as_ushort(h0) | ((uint32_t)__half_as_ushort(h1) << 16);
    lo = pack2h(e0 - __half2float(h0), e1 - __half2float(h1));
}

#define MMA_F16(acc, a0, a1, a2, a3, b0, b1)                                    \
    asm volatile(                                                               \
        "mma.sync.aligned.m16n8k16.row.col.f32.f16.f16.f32 "                    \
        "{%0,%1,%2,%3}, {%4,%5,%6,%7}, {%8,%9}, {%0,%1,%2,%3};"                 \
        : "+f"(acc[0]), "+f"(acc[1]), "+f"(acc[2]), "+f"(acc[3])                \
        : "r"(a0), "r"(a1), "r"(a2), "r"(a3), "r"(b0), "r"(b1))

// ---------------- launch 1: pack weights + zero counters --------------------
__global__ void k_pack(const float* __restrict__ Wl2, const float* __restrict__ Wr2,
                       const float* __restrict__ Wl3, const float* __restrict__ Wr3,
                       const float* __restrict__ W1,  const float* __restrict__ W2) {
    int i = blockIdx.x * blockDim.x + threadIdx.x;
    int stride = gridDim.x * blockDim.x;
    const float* Ws[6] = {Wl2, Wr2, Wl3, Wr3, W1, W1 + 256 * HD};
    for (int j = i; j < 32768; j += stride) {
        int k2 = j >> 8, n = j & 255;
        int i0 = (k2 << 9) + n, i1 = i0 + 256;
#pragma unroll
        for (int w = 0; w < 6; w++) {
            uint32_t hi, lo;
            packhl(Ws[w][i0], Ws[w][i1], hi, lo);
            g_wph[w * 32768 + j] = hi;
            g_wpl[w * 32768 + j] = lo;
        }
    }
    for (int j = i; j < 16384; j += stride) {
        int k2 = j >> 7, n = j & 127;
        g_w2p[j] = pack2h(W2[(k2 << 8) + n], W2[(k2 << 8) + 128 + n]);
    }
    for (int j = i; j < NN; j += stride) g_cnt[j] = 0;
}

// ---------------- launch 2: decode + bucket fill ----------------------------
__global__ void k_idx_fill(const void* __restrict__ eiv) {
    __shared__ int is64_s;
    const int tid = threadIdx.x;
    if (tid == 0) is64_s = 1;
    __syncthreads();
    {
        const int* w = (const int*)eiv;
        if (w[2 * tid + 1] != 0) is64_s = 0;
    }
    __syncthreads();
    const int is64 = is64_s;

    int e = blockIdx.x * blockDim.x + tid;
    if (e < NE) {
        int r, c;
        if (is64) {
            const long long* ei = (const long long*)eiv;
            r = (int)ei[e];
            c = (int)ei[NE + e];
        } else {
            const int* ei = (const int*)eiv;
            r = ei[e];
            c = ei[NE + e];
        }
        r = min(max(r, 0), NN - 1);
        c = min(max(c, 0), NN - 1);
        g_row[e] = r;
        g_col[e] = c;
        int pos = atomicAdd(&g_cnt[c], 1);
        if (pos < MAXDEG) g_elist[c * MAXDEG + pos] = r;
    }
}

// ---------------- launch 3: layer 1 (d_in=3), warp per node -----------------
__global__ void k_sage1(const float* __restrict__ x, const float* __restrict__ Wl,
                        const float* __restrict__ bl, const float* __restrict__ Wr) {
    const int node = blockIdx.x * 8 + (threadIdx.x >> 5);
    const int lane = threadIdx.x & 31;
    if (node >= NN) return;
    const int cnt = g_cnt[node];
    const int deg = min(cnt, MAXDEG);
    float inv = 1.f / fmaxf((float)cnt, 1.f);
    if (lane == 0) g_inv[node] = inv;

    float s0 = 0.f, s1 = 0.f, s2 = 0.f;
    const int* el = g_elist + node * MAXDEG;
    for (int j = lane; j < deg; j += 32) {
        int s = el[j];
        s0 += x[3 * s + 0];
        s1 += x[3 * s + 1];
        s2 += x[3 * s + 2];
    }
#pragma unroll
    for (int o = 16; o > 0; o >>= 1) {
        s0 += __shfl_xor_sync(0xffffffff, s0, o);
        s1 += __shfl_xor_sync(0xffffffff, s1, o);
        s2 += __shfl_xor_sync(0xffffffff, s2, o);
    }
    const float a0 = s0 * inv, a1 = s1 * inv, a2 = s2 * inv;
    const float x0 = x[3 * node + 0], x1 = x[3 * node + 1], x2 = x[3 * node + 2];

    int c = lane * 8;
#pragma unroll
    for (int h = 0; h < 2; h++) {
        int cc = c + h * 4;
        float4 b = *(const float4*)(bl + cc);
        float4 wl0 = *(const float4*)(Wl + 0 * HD + cc);
        float4 wl1 = *(const float4*)(Wl + 1 * HD + cc);
        float4 wl2 = *(const float4*)(Wl + 2 * HD + cc);
        float4 wr0 = *(const float4*)(Wr + 0 * HD + cc);
        float4 wr1 = *(const float4*)(Wr + 1 * HD + cc);
        float4 wr2 = *(const float4*)(Wr + 2 * HD + cc);
        float4 o;
        o.x = fmaxf(b.x + a0 * wl0.x + a1 * wl1.x + a2 * wl2.x + x0 * wr0.x + x1 * wr1.x + x2 * wr2.x, 0.f);
        o.y = fmaxf(b.y + a0 * wl0.y + a1 * wl1.y + a2 * wl2.y + x0 * wr0.y + x1 * wr1.y + x2 * wr2.y, 0.f);
        o.z = fmaxf(b.z + a0 * wl0.z + a1 * wl1.z + a2 * wl2.z + x0 * wr0.z + x1 * wr1.z + x2 * wr2.z, 0.f);
        o.w = fmaxf(b.w + a0 * wl0.w + a1 * wl1.w + a2 * wl2.w + x0 * wr0.w + x1 * wr1.w + x2 * wr2.w, 0.f);
        *(float4*)(g_hA + (size_t)node * HD + cc) = o;
        uint32_t hi0, lo0, hi1, lo1;
        packhl(o.x, o.y, hi0, lo0);
        packhl(o.z, o.w, hi1, lo1);
        int k2 = cc >> 1;
        g_pAh[node * 128 + k2]     = hi0;  g_pAl[node * 128 + k2]     = lo0;
        g_pAh[node * 128 + k2 + 1] = hi1;  g_pAl[node * 128 + k2 + 1] = lo1;
    }
}

// Gather aggregation (atomic-free). Warp per node. Output packed hi/lo.
__global__ void k_gather(int src) {
    const float4* h4 = (const float4*)(src ? g_hB : g_hA);
    const int lane = threadIdx.x & 31;
    const int node = blockIdx.x * 8 + (threadIdx.x >> 5);
    if (node >= NN) return;
    const int deg = min(g_cnt[node], MAXDEG);
    const float inv = g_inv[node];
    const int* el = g_elist + node * MAXDEG;
    float4 a0 = make_float4(0.f, 0.f, 0.f, 0.f);
    float4 a1 = make_float4(0.f, 0.f, 0.f, 0.f);
    for (int j = 0; j < deg; j++) {
        int s = el[j];
        float4 v0 = h4[(size_t)s * 64 + lane];
        float4 v1 = h4[(size_t)s * 64 + 32 + lane];
        a0.x += v0.x; a0.y += v0.y; a0.z += v0.z; a0.w += v0.w;
        a1.x += v1.x; a1.y += v1.y; a1.z += v1.z; a1.w += v1.w;
    }
    a0.x *= inv; a0.y *= inv; a0.z *= inv; a0.w *= inv;
    a1.x *= inv; a1.y *= inv; a1.z *= inv; a1.w *= inv;
    uint32_t hi, lo;
    int base = node * 128 + lane * 2;
    packhl(a0.x, a0.y, hi, lo); g_pGh[base]      = hi; g_pGl[base]      = lo;
    packhl(a0.z, a0.w, hi, lo); g_pGh[base + 1]  = hi; g_pGl[base + 1]  = lo;
    packhl(a1.x, a1.y, hi, lo); g_pGh[base + 64] = hi; g_pGl[base + 64] = lo;
    packhl(a1.z, a1.w, hi, lo); g_pGh[base + 65] = hi; g_pGl[base + 65] = lo;
}

// ---------------------------------------------------------------------------
// SAGE layer, fp16 m16n8k16 mma.sync, 3-term split (R13/R15 config, unchanged).
// ---------------------------------------------------------------------------
__global__ void k_sage_tc(int lay, const float* __restrict__ bl) {
    const uint32_t* hph = lay ? g_pBh : g_pAh;
    const uint32_t* hpl = lay ? g_pBl : g_pAl;
    uint32_t* outph = lay ? g_pAh : g_pBh;
    uint32_t* outpl = lay ? g_pAl : g_pBl;
    const int wsel = lay * 2;
    __shared__ uint32_t Ah[64 * 20], Al[64 * 20];
    __shared__ uint32_t Bh[16 * 136], Bl[16 * 136];

    const int tid = threadIdx.x;
    const int m0 = blockIdx.y * 64;
    const int n0 = blockIdx.x * 128;
    const int lane = tid & 31, wid = tid >> 5;
    const int mblk = wid >> 1, nhalf = wid & 1;
    const int g = lane >> 2, t = lane & 3;
    const int arow = tid >> 2, ak2 = (tid & 3) << 2;
    const int mA = m0 + arow;
    const bool mok = (mA < NN);
    const int brow = tid >> 4, bc8 = (tid & 15) << 3;
    float acc[8][4] = {};

    for (int kk = 0; kk < 512; kk += 32) {
        {
            int aidx = arow * 20 + ak2;
            if (mok) {
                size_t off = (size_t)mA * 128 + ((kk & 255) >> 1) + ak2;
                const uint32_t* sh = (kk < 256) ? (g_pGh + off) : (hph + off);
                const uint32_t* sl = (kk < 256) ? (g_pGl + off) : (hpl + off);
                *(uint4*)&Ah[aidx] = *(const uint4*)sh;
                *(uint4*)&Al[aidx] = *(const uint4*)sl;
            } else {
                *(uint4*)&Ah[aidx] = make_uint4(0, 0, 0, 0);
                *(uint4*)&Al[aidx] = make_uint4(0, 0, 0, 0);
            }
        }
        {
            const uint32_t* Wh = g_wph + (size_t)(wsel + ((kk < 256) ? 0 : 1)) * 32768;
            const uint32_t* Wo = g_wpl + (size_t)(wsel + ((kk < 256) ? 0 : 1)) * 32768;
            size_t off = (size_t)(((kk & 255) >> 1) + brow) * 256 + n0 + bc8;
            *(uint4*)&Bh[brow * 136 + bc8]     = *(const uint4*)(Wh + off);
            *(uint4*)&Bh[brow * 136 + bc8 + 4] = *(const uint4*)(Wh + off + 4);
            *(uint4*)&Bl[brow * 136 + bc8]     = *(const uint4*)(Wo + off);
            *(uint4*)&Bl[brow * 136 + bc8 + 4] = *(const uint4*)(Wo + off + 4);
        }
        __syncthreads();
#pragma unroll
        for (int ks = 0; ks < 2; ks++) {
            int c0 = 8 * ks + t;
            int r0 = mblk * 16 + g;
            uint32_t ah0 = Ah[r0 * 20 + c0],       ah1 = Ah[(r0 + 8) * 20 + c0];
            uint32_t ah2 = Ah[r0 * 20 + c0 + 4],   ah3 = Ah[(r0 + 8) * 20 + c0 + 4];
            uint32_t al0 = Al[r0 * 20 + c0],       al1 = Al[(r0 + 8) * 20 + c0];
            uint32_t al2 = Al[r0 * 20 + c0 + 4],   al3 = Al[(r0 + 8) * 20 + c0 + 4];
#pragma unroll
            for (int nb = 0; nb < 8; nb++) {
                int nc = nhalf * 64 + nb * 8 + g;
                uint32_t bh0 = Bh[(8 * ks + t) * 136 + nc];
                uint32_t bh1 = Bh[(8 * ks + t + 4) * 136 + nc];
                uint32_t bl0 = Bl[(8 * ks + t) * 136 + nc];
                uint32_t bl1 = Bl[(8 * ks + t + 4) * 136 + nc];
                MMA_F16(acc[nb], ah0, ah1, ah2, ah3, bh0, bh1);
                MMA_F16(acc[nb], ah0, ah1, ah2, ah3, bl0, bl1);
                MMA_F16(acc[nb], al0, al1, al2, al3, bh0, bh1);
            }
        }
        __syncthreads();
    }
    int row0 = m0 + mblk * 16 + g;
#pragma unroll
    for (int nb = 0; nb < 8; nb++) {
        int col = n0 + nhalf * 64 + nb * 8 + 2 * t;
        int k2 = col >> 1;
        float bla = bl[col], blb = bl[col + 1];
        if (row0 < NN) {
            float v0 = fmaxf(acc[nb][0] + bla, 0.f);
            float v1 = fmaxf(acc[nb][1] + blb, 0.f);
            if (lay == 0) { g_hB[row0 * HD + col] = v0; g_hB[row0 * HD + col + 1] = v1; }
            uint32_t hi, lo;
            packhl(v0, v1, hi, lo);
            outph[row0 * 128 + k2] = hi;
            outpl[row0 * 128 + k2] = lo;
        }
        if (row0 + 8 < NN) {
            float v0 = fmaxf(acc[nb][2] + bla, 0.f);
            float v1 = fmaxf(acc[nb][3] + blb, 0.f);
            if (lay == 0) { g_hB[(row0 + 8) * HD + col] = v0; g_hB[(row0 + 8) * HD + col + 1] = v1; }
            uint32_t hi, lo;
            packhl(v0, v1, hi, lo);
            outph[(row0 + 8) * 128 + k2] = hi;
            outpl[(row0 + 8) * 128 + k2] = lo;
        }
    }
}

// ---------------------------------------------------------------------------
// Fused projection, fp16 3-term (R13/R15 config, unchanged).
// ---------------------------------------------------------------------------
__global__ void k_proj_tc() {
    __shared__ uint32_t Ah[64 * 20], Al[64 * 20];
    __shared__ uint32_t Bh[16 * 136], Bl[16 * 136];

    const int tid = threadIdx.x;
    const int m0 = blockIdx.y * 64;
    const int n0 = blockIdx.x * 128;
    const int lane = tid & 31, wid = tid >> 5;
    const int mblk = wid >> 1, nhalf = wid & 1;
    const int g = lane >> 2, t = lane & 3;
    const int arow = tid >> 2, ak2 = (tid & 3) << 2;
    const int mA = m0 + arow;
    const bool mok = (mA < NN);
    const int brow = tid >> 4, bc8 = (tid & 15) << 3;
    const int wsel = 4 + (n0 >= 256 ? 1 : 0);
    const int nloc = n0 & 255;
    float acc[8][4] = {};

    for (int kk = 0; kk < 256; kk += 32) {
        {
            int aidx = arow * 20 + ak2;
            if (mok) {
                size_t off = (size_t)mA * 128 + (kk >> 1) + ak2;
                *(uint4*)&Ah[aidx] = *(const uint4*)(g_pAh + off);
                *(uint4*)&Al[aidx] = *(const uint4*)(g_pAl + off);
            } else {
                *(uint4*)&Ah[aidx] = make_uint4(0, 0, 0, 0);
                *(uint4*)&Al[aidx] = make_uint4(0, 0, 0, 0);
            }
        }
        {
            const uint32_t* Wh = g_wph + (size_t)wsel * 32768;
            const uint32_t* Wo = g_wpl + (size_t)wsel * 32768;
            size_t off = (size_t)((kk >> 1) + brow) * 256 + nloc + bc8;
            *(uint4*)&Bh[brow * 136 + bc8]     = *(const uint4*)(Wh + off);
            *(uint4*)&Bh[brow * 136 + bc8 + 4] = *(const uint4*)(Wh + off + 4);
            *(uint4*)&Bl[brow * 136 + bc8]     = *(const uint4*)(Wo + off);
            *(uint4*)&Bl[brow * 136 + bc8 + 4] = *(const uint4*)(Wo + off + 4);
        }
        __syncthreads();
#pragma unroll
        for (int ks = 0; ks < 2; ks++) {
            int c0 = 8 * ks + t;
            int r0 = mblk * 16 + g;
            uint32_t ah0 = Ah[r0 * 20 + c0],     ah1 = Ah[(r0 + 8) * 20 + c0];
            uint32_t ah2 = Ah[r0 * 20 + c0 + 4], ah3 = Ah[(r0 + 8) * 20 + c0 + 4];
            uint32_t al0 = Al[r0 * 20 + c0],     al1 = Al[(r0 + 8) * 20 + c0];
            uint32_t al2 = Al[r0 * 20 + c0 + 4], al3 = Al[(r0 + 8) * 20 + c0 + 4];
#pragma unroll
            for (int nb = 0; nb < 8; nb++) {
                int nc = nhalf * 64 + nb * 8 + g;
                uint32_t bh0 = Bh[(8 * ks + t) * 136 + nc];
                uint32_t bh1 = Bh[(8 * ks + t + 4) * 136 + nc];
                uint32_t bl0 = Bl[(8 * ks + t) * 136 + nc];
                uint32_t bl1 = Bl[(8 * ks + t + 4) * 136 + nc];
                MMA_F16(acc[nb], ah0, ah1, ah2, ah3, bh0, bh1);
                MMA_F16(acc[nb], ah0, ah1, ah2, ah3, bl0, bl1);
                MMA_F16(acc[nb], al0, al1, al2, al3, bh0, bh1);
            }
        }
        __syncthreads();
    }
    int row0 = m0 + mblk * 16 + g;
#pragma unroll
    for (int nb = 0; nb < 8; nb++) {
        int col = n0 + nhalf * 64 + nb * 8 + 2 * t;
        float* dst = (col < 256) ? (g_hB + col) : (g_aggr + col - 256);
        if (row0 < NN) {
            dst[row0 * HD]     = acc[nb][0];
            dst[row0 * HD + 1] = acc[nb][1];
        }
        if (row0 + 8 < NN) {
            dst[(row0 + 8) * HD]     = acc[nb][2];
            dst[(row0 + 8) * HD + 1] = acc[nb][3];
        }
    }
}

// ---------------------------------------------------------------------------
// Fused edge kernel: W2 fully resident in smem (loaded once), A double-buffered,
// ONE sync per chunk. Fragment layout/math identical to R15.
// Dynamic smem: W2s[128*136] | A0[128*20] | A1[128*20] | rs|cs|eas|w512s|bases
// ---------------------------------------------------------------------------
#define EW2   0
#define EA0   17408
#define EA1   (17408 + 2560)
#define ERS   (17408 + 5120)
#define ECS   (ERS + 128)
#define EEA   (ECS + 128)
#define EW512 (EEA + 128)
#define EBASE (EW512 + 256)
#define EWORDS (EBASE + 256)     // 23424 words = 93696 B

__global__ void __launch_bounds__(256, 1) k_edge(
        const float* __restrict__ ea, const float* __restrict__ tdp,
        const float* __restrict__ W1, const float* __restrict__ b1,
        const float* __restrict__ b2, const float* __restrict__ W3,
        const float* __restrict__ b3, float* __restrict__ out) {
    extern __shared__ uint32_t sm[];
    uint32_t* W2s = sm + EW2;
    uint32_t* Abuf[2] = {sm + EA0, sm + EA1};
    int*   rs    = (int*)(sm + ERS);
    int*   cs    = (int*)(sm + ECS);
    float* eas   = (float*)(sm + EEA);
    float* w512s = (float*)(sm + EW512);
    float* bases = (float*)(sm + EBASE);

    const int tid = threadIdx.x;
    const int m0 = blockIdx.x * 128;
    const float tdv = tdp[0];

    // one-time fills
    if (tid < 128) {
        int m = m0 + tid;
        if (m < NE) { rs[tid] = g_row[m]; cs[tid] = g_col[m]; eas[tid] = ea[m]; }
        else        { rs[tid] = 0;        cs[tid] = 0;        eas[tid] = 0.f;  }
    }
    w512s[tid] = W1[512 * HD + tid];
    bases[tid] = b1[tid] + tdv * W1[513 * HD + tid];
    // W2 resident: 4096 uint4, 16 per thread
#pragma unroll
    for (int p = 0; p < 16; p++) {
        int j4 = tid + p * 256;
        int row = j4 >> 5, col4 = j4 & 31;
        *(uint4*)&W2s[row * 136 + col4 * 4] = ((const uint4*)g_w2p)[j4];
    }
    __syncthreads();

    const int lane = tid & 31;
    const int wid  = tid >> 5;
    const int g = lane >> 2, t = lane & 3;
    float acc[16][4] = {};

    const int arow = tid >> 1;
    const int half = tid & 1;
    const float* p1r = g_hB   + (size_t)rs[arow] * HD;
    const float* p2r = g_aggr + (size_t)cs[arow] * HD;
    const float eav = eas[arow];

    // construct chunk c's A into dst
    auto constructA = [&](int c, uint32_t* dst) {
#pragma unroll
        for (int q = 0; q < 4; q++) {
            int kb = c * 32 + half * 16 + 4 * q;
            float4 u = *(const float4*)(p1r + kb);
            float4 v = *(const float4*)(p2r + kb);
            float z0 = fmaxf(u.x + v.x + eav * w512s[kb + 0] + bases[kb + 0], 0.f);
            float z1 = fmaxf(u.y + v.y + eav * w512s[kb + 1] + bases[kb + 1], 0.f);
            float z2 = fmaxf(u.z + v.z + eav * w512s[kb + 2] + bases[kb + 2], 0.f);
            float z3 = fmaxf(u.w + v.w + eav * w512s[kb + 3] + bases[kb + 3], 0.f);
            dst[arow * 20 + half * 8 + 2 * q]     = pack2h(z0, z1);
            dst[arow * 20 + half * 8 + 2 * q + 1] = pack2h(z2, z3);
        }
    };

    constructA(0, Abuf[0]);
    __syncthreads();

    for (int c = 0; c < 8; c++) {
        // prefetch next chunk's A (overlaps with mma below in the issue stream)
        if (c < 7) constructA(c + 1, Abuf[(c + 1) & 1]);
        const uint32_t* A32 = Abuf[c & 1];
#pragma unroll
        for (int ks = 0; ks < 2; ks++) {
            int c0 = 8 * ks + t;
            int r0 = wid * 16 + g;
            uint32_t a0 = A32[r0 * 20 + c0];
            uint32_t a1 = A32[(r0 + 8) * 20 + c0];
            uint32_t a2 = A32[r0 * 20 + c0 + 4];
            uint32_t a3 = A32[(r0 + 8) * 20 + c0 + 4];
            int brow0 = c * 16 + 8 * ks + t;
#pragma unroll
            for (int nb = 0; nb < 16; nb++) {
                int nc = nb * 8 + g;
                uint32_t b0 = W2s[brow0 * 136 + nc];
                uint32_t b1r = W2s[(brow0 + 4) * 136 + nc];
                MMA_F16(acc[nb], a0, a1, a2, a3, b0, b1r);
            }
        }
        __syncthreads();
    }

    // epilogue: relu(acc + b2) dot W3 over 128 cols, quad-reduce
    float pr0 = 0.f, pr1 = 0.f;
#pragma unroll
    for (int nb = 0; nb < 16; nb++) {
        int ncol = nb * 8 + 2 * t;
        float w3a = W3[ncol], w3b = W3[ncol + 1];
        float b2a = b2[ncol], b2b = b2[ncol + 1];
        pr0 += fmaxf(acc[nb][0] + b2a, 0.f) * w3a + fmaxf(acc[nb][1] + b2b, 0.f) * w3b;
        pr1 += fmaxf(acc[nb][2] + b2a, 0.f) * w3a + fmaxf(acc[nb][3] + b2b, 0.f) * w3b;
    }
    pr0 += __shfl_xor_sync(0xffffffff, pr0, 1);
    pr0 += __shfl_xor_sync(0xffffffff, pr0, 2);
    pr1 += __shfl_xor_sync(0xffffffff, pr1, 1);
    pr1 += __shfl_xor_sync(0xffffffff, pr1, 2);
    if (t == 0) {
        float b3v = b3[0];
        int m = m0 + wid * 16 + g;
        if (m < NE) out[m] = pr0 + b3v;
        if (m + 8 < NE) out[m + 8] = pr1 + b3v;
    }
}

// ---------------- host launcher ---------------------------------------------
extern "C" void kernel_launch(void* const* d_in, const int* in_sizes, int n_in,
                              void* d_out, int out_size) {
    const float* x   = (const float*)d_in[0];
    const void*  ei  = d_in[1];
    const float* ea  = (const float*)d_in[2];
    const float* td  = (const float*)d_in[3];
    const float* Wl1 = (const float*)d_in[4];
    const float* bl1 = (const float*)d_in[5];
    const float* Wr1 = (const float*)d_in[6];
    const float* Wl2 = (const float*)d_in[7];
    const float* bl2 = (const float*)d_in[8];
    const float* Wr2 = (const float*)d_in[9];
    const float* Wl3 = (const float*)d_in[10];
    const float* bl3 = (const float*)d_in[11];
    const float* Wr3 = (const float*)d_in[12];
    const float* W1  = (const float*)d_in[13];
    const float* b1  = (const float*)d_in[14];
    const float* W2  = (const float*)d_in[15];
    const float* b2  = (const float*)d_in[16];
    const float* W3  = (const float*)d_in[17];
    const float* b3  = (const float*)d_in[18];
    float* out = (float*)d_out;

    const int ESMEM = EWORDS * 4;
    static int attr_done = 0;
    if (!attr_done) {
        cudaFuncSetAttribute(k_edge, cudaFuncAttributeMaxDynamicSharedMemorySize, ESMEM);
        attr_done = 1;
    }

    k_pack<<<256, 256>>>(Wl2, Wr2, Wl3, Wr3, W1, W2);          // 1 (also zeros g_cnt)
    k_idx_fill<<<(NE + 255) / 256, 256>>>(ei);                  // 2
    k_sage1<<<(NN + 7) / 8, 256>>>(x, Wl1, bl1, Wr1);           // 3 -> g_hA, g_pA

    dim3 gs_tc(HD / 128, (NN + 63) / 64);                       // (2, 313)

    k_gather<<<(NN + 7) / 8, 256>>>(0);                         // 4 -> g_pG
    k_sage_tc<<<gs_tc, 256>>>(0, bl2);                          // 5 -> g_hB, g_pB
    k_gather<<<(NN + 7) / 8, 256>>>(1);                         // 6 -> g_pG
    k_sage_tc<<<gs_tc, 256>>>(1, bl3);                          // 7 -> g_pA

    dim3 gp_tc(4, (NN + 63) / 64);
    k_proj_tc<<<gp_tc, 256>>>();                                // 8 -> g_hB (P1), g_aggr (P2)

    k_edge<<<(NE + 127) / 128, 256, ESMEM>>>(ea, td, W1, b1, b2, W3, b3, out);  // 9
}

// round 17
// speedup vs baseline: 1.3467x; 1.3467x over previous
#include <cuda_runtime.h>
#include <cuda_fp16.h>
#include <cstdint>

#define NN 20000
#define NE 300000
#define HD 256
#define MAXDEG 96

// ---------------- scratch (device globals; referenced ONLY in device code) --
__device__ int   g_cnt[NN];
__device__ __align__(16) float g_inv[NN];
__device__ __align__(16) float g_aggr[NN * HD];   // P2 (proj output)
__device__ __align__(16) float g_hA[NN * HD];     // layer1 h fp32 (for gather0)
__device__ __align__(16) float g_hB[NN * HD];     // layer2 h fp32 (for gather1); later P1
__device__ int g_row[NE];
__device__ int g_col[NE];
__device__ int g_elist[NN * MAXDEG];
// packed fp16 activations, K-pair-major: [node][k2]
__device__ __align__(16) uint32_t g_pAh[NN * 128], g_pAl[NN * 128]; // layer1 h, then layer3 h
__device__ __align__(16) uint32_t g_pBh[NN * 128], g_pBl[NN * 128]; // layer2 h
__device__ __align__(16) uint32_t g_pGh[NN * 128], g_pGl[NN * 128]; // gathered aggr
// packed fp16 weights (hi only), K-pair-major
// order: 0=Wl2 1=Wr2 2=Wl3 3=Wr3 4=W1a 5=W1b (each 128x256 uint32)
__device__ __align__(16) uint32_t g_wph[6 * 32768];
__device__ __align__(16) uint32_t g_w2p[16384];   // W2 [128 k2][128 n]

__device__ __forceinline__ uint32_t pack2h(float e0, float e1) {
    __half h0 = __float2half_rn(e0), h1 = __float2half_rn(e1);
    return (uint32_t)__half_as_ushort(h0) | ((uint32_t)__half_as_ushort(h1) << 16);
}
__device__ __forceinline__ void packhl(float e0, float e1, uint32_t& hi, uint32_t& lo) {
    __half h0 = __float2half_rn(e0), h1 = __float2half_rn(e1);
    hi = (uint32_t)__half_as_ushort(h0) | ((uint32_t)__half_as_ushort(h1) << 16);
    lo = pack2h(e0 - __half2float(h0), e1 - __half2float(h1));
}

#define MMA_F16(acc, a0, a1, a2, a3, b0, b1)                                    \
    asm volatile(                                                               \
        "mma.sync.aligned.m16n8k16.row.col.f32.f16.f16.f32 "                    \
        "{%0,%1,%2,%3}, {%4,%5,%6,%7}, {%8,%9}, {%0,%1,%2,%3};"                 \
        : "+f"(acc[0]), "+f"(acc[1]), "+f"(acc[2]), "+f"(acc[3])                \
        : "r"(a0), "r"(a1), "r"(a2), "r"(a3), "r"(b0), "r"(b1))

// ---------------- launch 1: pack weights (hi only) + zero counters ----------
__global__ void k_pack(const float* __restrict__ Wl2, const float* __restrict__ Wr2,
                       const float* __restrict__ Wl3, const float* __restrict__ Wr3,
                       const float* __restrict__ W1,  const float* __restrict__ W2) {
    int i = blockIdx.x * blockDim.x + threadIdx.x;
    int stride = gridDim.x * blockDim.x;
    const float* Ws[6] = {Wl2, Wr2, Wl3, Wr3, W1, W1 + 256 * HD};
    for (int j = i; j < 32768; j += stride) {
        int k2 = j >> 8, n = j & 255;
        int i0 = (k2 << 9) + n, i1 = i0 + 256;
#pragma unroll
        for (int w = 0; w < 6; w++)
            g_wph[w * 32768 + j] = pack2h(Ws[w][i0], Ws[w][i1]);
    }
    for (int j = i; j < 16384; j += stride) {
        int k2 = j >> 7, n = j & 127;
        g_w2p[j] = pack2h(W2[(k2 << 8) + n], W2[(k2 << 8) + 128 + n]);
    }
    for (int j = i; j < NN; j += stride) g_cnt[j] = 0;
}

// ---------------- launch 2: decode + bucket fill ----------------------------
__global__ void k_idx_fill(const void* __restrict__ eiv) {
    __shared__ int is64_s;
    const int tid = threadIdx.x;
    if (tid == 0) is64_s = 1;
    __syncthreads();
    {
        const int* w = (const int*)eiv;
        if (w[2 * tid + 1] != 0) is64_s = 0;
    }
    __syncthreads();
    const int is64 = is64_s;

    int e = blockIdx.x * blockDim.x + tid;
    if (e < NE) {
        int r, c;
        if (is64) {
            const long long* ei = (const long long*)eiv;
            r = (int)ei[e];
            c = (int)ei[NE + e];
        } else {
            const int* ei = (const int*)eiv;
            r = ei[e];
            c = ei[NE + e];
        }
        r = min(max(r, 0), NN - 1);
        c = min(max(c, 0), NN - 1);
        g_row[e] = r;
        g_col[e] = c;
        int pos = atomicAdd(&g_cnt[c], 1);
        if (pos < MAXDEG) g_elist[c * MAXDEG + pos] = r;
    }
}

// ---------------- launch 3: layer 1 (d_in=3), warp per node -----------------
__global__ void k_sage1(const float* __restrict__ x, const float* __restrict__ Wl,
                        const float* __restrict__ bl, const float* __restrict__ Wr) {
    const int node = blockIdx.x * 8 + (threadIdx.x >> 5);
    const int lane = threadIdx.x & 31;
    if (node >= NN) return;
    const int cnt = g_cnt[node];
    const int deg = min(cnt, MAXDEG);
    float inv = 1.f / fmaxf((float)cnt, 1.f);
    if (lane == 0) g_inv[node] = inv;

    float s0 = 0.f, s1 = 0.f, s2 = 0.f;
    const int* el = g_elist + node * MAXDEG;
    for (int j = lane; j < deg; j += 32) {
        int s = el[j];
        s0 += x[3 * s + 0];
        s1 += x[3 * s + 1];
        s2 += x[3 * s + 2];
    }
#pragma unroll
    for (int o = 16; o > 0; o >>= 1) {
        s0 += __shfl_xor_sync(0xffffffff, s0, o);
        s1 += __shfl_xor_sync(0xffffffff, s1, o);
        s2 += __shfl_xor_sync(0xffffffff, s2, o);
    }
    const float a0 = s0 * inv, a1 = s1 * inv, a2 = s2 * inv;
    const float x0 = x[3 * node + 0], x1 = x[3 * node + 1], x2 = x[3 * node + 2];

    int c = lane * 8;
#pragma unroll
    for (int h = 0; h < 2; h++) {
        int cc = c + h * 4;
        float4 b = *(const float4*)(bl + cc);
        float4 wl0 = *(const float4*)(Wl + 0 * HD + cc);
        float4 wl1 = *(const float4*)(Wl + 1 * HD + cc);
        float4 wl2 = *(const float4*)(Wl + 2 * HD + cc);
        float4 wr0 = *(const float4*)(Wr + 0 * HD + cc);
        float4 wr1 = *(const float4*)(Wr + 1 * HD + cc);
        float4 wr2 = *(const float4*)(Wr + 2 * HD + cc);
        float4 o;
        o.x = fmaxf(b.x + a0 * wl0.x + a1 * wl1.x + a2 * wl2.x + x0 * wr0.x + x1 * wr1.x + x2 * wr2.x, 0.f);
        o.y = fmaxf(b.y + a0 * wl0.y + a1 * wl1.y + a2 * wl2.y + x0 * wr0.y + x1 * wr1.y + x2 * wr2.y, 0.f);
        o.z = fmaxf(b.z + a0 * wl0.z + a1 * wl1.z + a2 * wl2.z + x0 * wr0.z + x1 * wr1.z + x2 * wr2.z, 0.f);
        o.w = fmaxf(b.w + a0 * wl0.w + a1 * wl1.w + a2 * wl2.w + x0 * wr0.w + x1 * wr1.w + x2 * wr2.w, 0.f);
        *(float4*)(g_hA + (size_t)node * HD + cc) = o;
        uint32_t hi0, lo0, hi1, lo1;
        packhl(o.x, o.y, hi0, lo0);
        packhl(o.z, o.w, hi1, lo1);
        int k2 = cc >> 1;
        g_pAh[node * 128 + k2]     = hi0;  g_pAl[node * 128 + k2]     = lo0;
        g_pAh[node * 128 + k2 + 1] = hi1;  g_pAl[node * 128 + k2 + 1] = lo1;
    }
}

// Gather aggregation (atomic-free). Warp per node. Output packed hi/lo.
__global__ void k_gather(int src) {
    const float4* h4 = (const float4*)(src ? g_hB : g_hA);
    const int lane = threadIdx.x & 31;
    const int node = blockIdx.x * 8 + (threadIdx.x >> 5);
    if (node >= NN) return;
    const int deg = min(g_cnt[node], MAXDEG);
    const float inv = g_inv[node];
    const int* el = g_elist + node * MAXDEG;
    float4 a0 = make_float4(0.f, 0.f, 0.f, 0.f);
    float4 a1 = make_float4(0.f, 0.f, 0.f, 0.f);
    for (int j = 0; j < deg; j++) {
        int s = el[j];
        float4 v0 = h4[(size_t)s * 64 + lane];
        float4 v1 = h4[(size_t)s * 64 + 32 + lane];
        a0.x += v0.x; a0.y += v0.y; a0.z += v0.z; a0.w += v0.w;
        a1.x += v1.x; a1.y += v1.y; a1.z += v1.z; a1.w += v1.w;
    }
    a0.x *= inv; a0.y *= inv; a0.z *= inv; a0.w *= inv;
    a1.x *= inv; a1.y *= inv; a1.z *= inv; a1.w *= inv;
    uint32_t hi, lo;
    int base = node * 128 + lane * 2;
    packhl(a0.x, a0.y, hi, lo); g_pGh[base]      = hi; g_pGl[base]      = lo;
    packhl(a0.z, a0.w, hi, lo); g_pGh[base + 1]  = hi; g_pGl[base + 1]  = lo;
    packhl(a1.x, a1.y, hi, lo); g_pGh[base + 64] = hi; g_pGl[base + 64] = lo;
    packhl(a1.z, a1.w, hi, lo); g_pGh[base + 65] = hi; g_pGl[base + 65] = lo;
}

// ---------------------------------------------------------------------------
// SAGE layer, fp16 m16n8k16, 2-term split (weights single fp16, activations
// hi+lo): acc = ah*bh + al*bh. R15 structure otherwise unchanged.
// ---------------------------------------------------------------------------
__global__ void k_sage_tc(int lay, const float* __restrict__ bl) {
    const uint32_t* hph = lay ? g_pBh : g_pAh;
    const uint32_t* hpl = lay ? g_pBl : g_pAl;
    uint32_t* outph = lay ? g_pAh : g_pBh;
    uint32_t* outpl = lay ? g_pAl : g_pBl;
    const int wsel = lay * 2;
    __shared__ uint32_t Ah[64 * 20], Al[64 * 20];
    __shared__ uint32_t Bh[16 * 136];

    const int tid = threadIdx.x;
    const int m0 = blockIdx.y * 64;
    const int n0 = blockIdx.x * 128;
    const int lane = tid & 31, wid = tid >> 5;
    const int mblk = wid >> 1, nhalf = wid & 1;
    const int g = lane >> 2, t = lane & 3;
    const int arow = tid >> 2, ak2 = (tid & 3) << 2;
    const int mA = m0 + arow;
    const bool mok = (mA < NN);
    const int brow = tid >> 4, bc8 = (tid & 15) << 3;
    float acc[8][4] = {};

    for (int kk = 0; kk < 512; kk += 32) {
        {
            int aidx = arow * 20 + ak2;
            if (mok) {
                size_t off = (size_t)mA * 128 + ((kk & 255) >> 1) + ak2;
                const uint32_t* sh = (kk < 256) ? (g_pGh + off) : (hph + off);
                const uint32_t* sl = (kk < 256) ? (g_pGl + off) : (hpl + off);
                *(uint4*)&Ah[aidx] = *(const uint4*)sh;
                *(uint4*)&Al[aidx] = *(const uint4*)sl;
            } else {
                *(uint4*)&Ah[aidx] = make_uint4(0, 0, 0, 0);
                *(uint4*)&Al[aidx] = make_uint4(0, 0, 0, 0);
            }
        }
        {
            const uint32_t* Wh = g_wph + (size_t)(wsel + ((kk < 256) ? 0 : 1)) * 32768;
            size_t off = (size_t)(((kk & 255) >> 1) + brow) * 256 + n0 + bc8;
            *(uint4*)&Bh[brow * 136 + bc8]     = *(const uint4*)(Wh + off);
            *(uint4*)&Bh[brow * 136 + bc8 + 4] = *(const uint4*)(Wh + off + 4);
        }
        __syncthreads();
#pragma unroll
        for (int ks = 0; ks < 2; ks++) {
            int c0 = 8 * ks + t;
            int r0 = mblk * 16 + g;
            uint32_t ah0 = Ah[r0 * 20 + c0],       ah1 = Ah[(r0 + 8) * 20 + c0];
            uint32_t ah2 = Ah[r0 * 20 + c0 + 4],   ah3 = Ah[(r0 + 8) * 20 + c0 + 4];
            uint32_t al0 = Al[r0 * 20 + c0],       al1 = Al[(r0 + 8) * 20 + c0];
            uint32_t al2 = Al[r0 * 20 + c0 + 4],   al3 = Al[(r0 + 8) * 20 + c0 + 4];
#pragma unroll
            for (int nb = 0; nb < 8; nb++) {
                int nc = nhalf * 64 + nb * 8 + g;
                uint32_t bh0 = Bh[(8 * ks + t) * 136 + nc];
                uint32_t bh1 = Bh[(8 * ks + t + 4) * 136 + nc];
                MMA_F16(acc[nb], ah0, ah1, ah2, ah3, bh0, bh1);
                MMA_F16(acc[nb], al0, al1, al2, al3, bh0, bh1);
            }
        }
        __syncthreads();
    }
    int row0 = m0 + mblk * 16 + g;
#pragma unroll
    for (int nb = 0; nb < 8; nb++) {
        int col = n0 + nhalf * 64 + nb * 8 + 2 * t;
        int k2 = col >> 1;
        float bla = bl[col], blb = bl[col + 1];
        if (row0 < NN) {
            float v0 = fmaxf(acc[nb][0] + bla, 0.f);
            float v1 = fmaxf(acc[nb][1] + blb, 0.f);
            if (lay == 0) { g_hB[row0 * HD + col] = v0; g_hB[row0 * HD + col + 1] = v1; }
            uint32_t hi, lo;
            packhl(v0, v1, hi, lo);
            outph[row0 * 128 + k2] = hi;
            outpl[row0 * 128 + k2] = lo;
        }
        if (row0 + 8 < NN) {
            float v0 = fmaxf(acc[nb][2] + bla, 0.f);
            float v1 = fmaxf(acc[nb][3] + blb, 0.f);
            if (lay == 0) { g_hB[(row0 + 8) * HD + col] = v0; g_hB[(row0 + 8) * HD + col + 1] = v1; }
            uint32_t hi, lo;
            packhl(v0, v1, hi, lo);
            outph[(row0 + 8) * 128 + k2] = hi;
            outpl[(row0 + 8) * 128 + k2] = lo;
        }
    }
}

// ---------------------------------------------------------------------------
// Fused projection, fp16 2-term: [P1 | P2] = h3 @ [W1a | W1b].
// ---------------------------------------------------------------------------
__global__ void k_proj_tc() {
    __shared__ uint32_t Ah[64 * 20], Al[64 * 20];
    __shared__ uint32_t Bh[16 * 136];

    const int tid = threadIdx.x;
    const int m0 = blockIdx.y * 64;
    const int n0 = blockIdx.x * 128;
    const int lane = tid & 31, wid = tid >> 5;
    const int mblk = wid >> 1, nhalf = wid & 1;
    const int g = lane >> 2, t = lane & 3;
    const int arow = tid >> 2, ak2 = (tid & 3) << 2;
    const int mA = m0 + arow;
    const bool mok = (mA < NN);
    const int brow = tid >> 4, bc8 = (tid & 15) << 3;
    const int wsel = 4 + (n0 >= 256 ? 1 : 0);
    const int nloc = n0 & 255;
    float acc[8][4] = {};

    for (int kk = 0; kk < 256; kk += 32) {
        {
            int aidx = arow * 20 + ak2;
            if (mok) {
                size_t off = (size_t)mA * 128 + (kk >> 1) + ak2;
                *(uint4*)&Ah[aidx] = *(const uint4*)(g_pAh + off);
                *(uint4*)&Al[aidx] = *(const uint4*)(g_pAl + off);
            } else {
                *(uint4*)&Ah[aidx] = make_uint4(0, 0, 0, 0);
                *(uint4*)&Al[aidx] = make_uint4(0, 0, 0, 0);
            }
        }
        {
            const uint32_t* Wh = g_wph + (size_t)wsel * 32768;
            size_t off = (size_t)((kk >> 1) + brow) * 256 + nloc + bc8;
            *(uint4*)&Bh[brow * 136 + bc8]     = *(const uint4*)(Wh + off);
            *(uint4*)&Bh[brow * 136 + bc8 + 4] = *(const uint4*)(Wh + off + 4);
        }
        __syncthreads();
#pragma unroll
        for (int ks = 0; ks < 2; ks++) {
            int c0 = 8 * ks + t;
            int r0 = mblk * 16 + g;
            uint32_t ah0 = Ah[r0 * 20 + c0],     ah1 = Ah[(r0 + 8) * 20 + c0];
            uint32_t ah2 = Ah[r0 * 20 + c0 + 4], ah3 = Ah[(r0 + 8) * 20 + c0 + 4];
            uint32_t al0 = Al[r0 * 20 + c0],     al1 = Al[(r0 + 8) * 20 + c0];
            uint32_t al2 = Al[r0 * 20 + c0 + 4], al3 = Al[(r0 + 8) * 20 + c0 + 4];
#pragma unroll
            for (int nb = 0; nb < 8; nb++) {
                int nc = nhalf * 64 + nb * 8 + g;
                uint32_t bh0 = Bh[(8 * ks + t) * 136 + nc];
                uint32_t bh1 = Bh[(8 * ks + t + 4) * 136 + nc];
                MMA_F16(acc[nb], ah0, ah1, ah2, ah3, bh0, bh1);
                MMA_F16(acc[nb], al0, al1, al2, al3, bh0, bh1);
            }
        }
        __syncthreads();
    }
    int row0 = m0 + mblk * 16 + g;
#pragma unroll
    for (int nb = 0; nb < 8; nb++) {
        int col = n0 + nhalf * 64 + nb * 8 + 2 * t;
        float* dst = (col < 256) ? (g_hB + col) : (g_aggr + col - 256);
        if (row0 < NN) {
            dst[row0 * HD]     = acc[nb][0];
            dst[row0 * HD + 1] = acc[nb][1];
        }
        if (row0 + 8 < NN) {
            dst[(row0 + 8) * HD]     = acc[nb][2];
            dst[(row0 + 8) * HD + 1] = acc[nb][3];
        }
    }
}

// ---------------------------------------------------------------------------
// Fused edge kernel, single-pass fp16 (R15 config, byte-identical).
// ---------------------------------------------------------------------------
__global__ void k_edge(const float* __restrict__ ea, const float* __restrict__ tdp,
                       const float* __restrict__ W1, const float* __restrict__ b1,
                       const float* __restrict__ b2, const float* __restrict__ W3,
                       const float* __restrict__ b3, float* __restrict__ out) {
    __shared__ uint32_t A32[128 * 20];
    __shared__ uint32_t B32[16 * 136];
    __shared__ int   rs[128], cs[128];
    __shared__ float eas[128];
    __shared__ float w512s[256], bases[256];

    const int tid = threadIdx.x;
    const int m0 = blockIdx.x * 128;
    const float tdv = tdp[0];

    if (tid < 128) {
        int m = m0 + tid;
        if (m < NE) { rs[tid] = g_row[m]; cs[tid] = g_col[m]; eas[tid] = ea[m]; }
        else        { rs[tid] = 0;        cs[tid] = 0;        eas[tid] = 0.f;  }
    }
    for (int k = tid; k < 256; k += 256) {
        w512s[k] = W1[512 * HD + k];
        bases[k] = b1[k] + tdv * W1[513 * HD + k];
    }
    __syncthreads();

    const int lane = tid & 31;
    const int wid  = tid >> 5;
    const int g = lane >> 2, t = lane & 3;
    const int brow = tid >> 4, bc8 = (tid & 15) << 3;
    float acc[16][4] = {};

    const int arow = tid >> 1;
    const int half = tid & 1;
    const float* p1r = g_hB   + (size_t)rs[arow] * HD;
    const float* p2r = g_aggr + (size_t)cs[arow] * HD;
    const float eav = eas[arow];

    for (int kk = 0; kk < 256; kk += 32) {
        {
            size_t off = (size_t)((kk >> 1) + brow) * 128 + bc8;
            *(uint4*)&B32[brow * 136 + bc8]     = *(const uint4*)(g_w2p + off);
            *(uint4*)&B32[brow * 136 + bc8 + 4] = *(const uint4*)(g_w2p + off + 4);
        }
#pragma unroll
        for (int q = 0; q < 4; q++) {
            int kb = kk + half * 16 + 4 * q;
            float4 u = *(const float4*)(p1r + kb);
            float4 v = *(const float4*)(p2r + kb);
            float z0 = fmaxf(u.x + v.x + eav * w512s[kb + 0] + bases[kb + 0], 0.f);
            float z1 = fmaxf(u.y + v.y + eav * w512s[kb + 1] + bases[kb + 1], 0.f);
            float z2 = fmaxf(u.z + v.z + eav * w512s[kb + 2] + bases[kb + 2], 0.f);
            float z3 = fmaxf(u.w + v.w + eav * w512s[kb + 3] + bases[kb + 3], 0.f);
            A32[arow * 20 + half * 8 + 2 * q]     = pack2h(z0, z1);
            A32[arow * 20 + half * 8 + 2 * q + 1] = pack2h(z2, z3);
        }
        __syncthreads();
#pragma unroll
        for (int ks = 0; ks < 2; ks++) {
            int c0 = 8 * ks + t;
            int r0 = wid * 16 + g;
            uint32_t a0 = A32[r0 * 20 + c0];
            uint32_t a1 = A32[(r0 + 8) * 20 + c0];
            uint32_t a2 = A32[r0 * 20 + c0 + 4];
            uint32_t a3 = A32[(r0 + 8) * 20 + c0 + 4];
#pragma unroll
            for (int nb = 0; nb < 16; nb++) {
                int nc = nb * 8 + g;
                uint32_t b0 = B32[(8 * ks + t) * 136 + nc];
                uint32_t b1r = B32[(8 * ks + t + 4) * 136 + nc];
                MMA_F16(acc[nb], a0, a1, a2, a3, b0, b1r);
            }
        }
        __syncthreads();
    }

    float pr0 = 0.f, pr1 = 0.f;
#pragma unroll
    for (int nb = 0; nb < 16; nb++) {
        int ncol = nb * 8 + 2 * t;
        float w3a = W3[ncol], w3b = W3[ncol + 1];
        float b2a = b2[ncol], b2b = b2[ncol + 1];
        pr0 += fmaxf(acc[nb][0] + b2a, 0.f) * w3a + fmaxf(acc[nb][1] + b2b, 0.f) * w3b;
        pr1 += fmaxf(acc[nb][2] + b2a, 0.f) * w3a + fmaxf(acc[nb][3] + b2b, 0.f) * w3b;
    }
    pr0 += __shfl_xor_sync(0xffffffff, pr0, 1);
    pr0 += __shfl_xor_sync(0xffffffff, pr0, 2);
    pr1 += __shfl_xor_sync(0xffffffff, pr1, 1);
    pr1 += __shfl_xor_sync(0xffffffff, pr1, 2);
    if (t == 0) {
        float b3v = b3[0];
        int m = m0 + wid * 16 + g;
        if (m < NE) out[m] = pr0 + b3v;
        if (m + 8 < NE) out[m + 8] = pr1 + b3v;
    }
}

// ---------------- host launcher ---------------------------------------------
extern "C" void kernel_launch(void* const* d_in, const int* in_sizes, int n_in,
                              void* d_out, int out_size) {
    const float* x   = (const float*)d_in[0];
    const void*  ei  = d_in[1];
    const float* ea  = (const float*)d_in[2];
    const float* td  = (const float*)d_in[3];
    const float* Wl1 = (const float*)d_in[4];
    const float* bl1 = (const float*)d_in[5];
    const float* Wr1 = (const float*)d_in[6];
    const float* Wl2 = (const float*)d_in[7];
    const float* bl2 = (const float*)d_in[8];
    const float* Wr2 = (const float*)d_in[9];
    const float* Wl3 = (const float*)d_in[10];
    const float* bl3 = (const float*)d_in[11];
    const float* Wr3 = (const float*)d_in[12];
    const float* W1  = (const float*)d_in[13];
    const float* b1  = (const float*)d_in[14];
    const float* W2  = (const float*)d_in[15];
    const float* b2  = (const float*)d_in[16];
    const float* W3  = (const float*)d_in[17];
    const float* b3  = (const float*)d_in[18];
    float* out = (float*)d_out;

    k_pack<<<256, 256>>>(Wl2, Wr2, Wl3, Wr3, W1, W2);          // 1 (also zeros g_cnt)
    k_idx_fill<<<(NE + 255) / 256, 256>>>(ei);                  // 2
    k_sage1<<<(NN + 7) / 8, 256>>>(x, Wl1, bl1, Wr1);           // 3 -> g_hA, g_pA

    dim3 gs_tc(HD / 128, (NN + 63) / 64);                       // (2, 313)

    k_gather<<<(NN + 7) / 8, 256>>>(0);                         // 4 -> g_pG
    k_sage_tc<<<gs_tc, 256>>>(0, bl2);                          // 5 -> g_hB, g_pB
    k_gather<<<(NN + 7) / 8, 256>>>(1);                         // 6 -> g_pG
    k_sage_tc<<<gs_tc, 256>>>(1, bl3);                          // 7 -> g_pA

    dim3 gp_tc(4, (NN + 63) / 64);
    k_proj_tc<<<gp_tc, 256>>>();                                // 8 -> g_hB (P1), g_aggr (P2)

    k_edge<<<(NE + 127) / 128, 256>>>(ea, td, W1, b1, b2, W3, b3, out);  // 9
}